// round 3
// baseline (speedup 1.0000x reference)
#include <cuda_runtime.h>
#include <cstdint>

// Deterministic cross-chunk reduction scratch (no alloc, no float atomics).
#define MAX_B      64
#define MAX_CHUNKS 32
__device__ float g_partial_log[MAX_B * MAX_CHUNKS];
__device__ float g_partial_hit[MAX_B * MAX_CHUNKS];
__device__ int   g_count[MAX_B];          // zero-init; self-resetting per replay

#define THREADS 128

__global__ __launch_bounds__(THREADS)
void traj_score_fused(const float* __restrict__ u_pred,
                      const float* __restrict__ u_obs,
                      const float* __restrict__ h_arr,
                      const float* __restrict__ lam_arr,
                      const float* __restrict__ th_arr,
                      float* __restrict__ out,
                      int n_per, int chunk, int n_chunks, int B)
{
    const int e = blockIdx.x;           // element / segment id
    const int c = blockIdx.y;           // chunk id within segment
    const int start = c * chunk;
    int end = start + chunk;
    if (end > n_per) end = n_per;
    const int count = end - start;

    // Per-element constants
    const float h    = __ldg(&h_arr[e]);
    const float lam  = __ldg(&lam_arr[e]);
    const float th   = __ldg(&th_arr[e]);
    const float inv_th = 1.0f / th;
    const float coef = lam / (1.0f - __expf(-lam));   // lam / (1 - e^-lam)
    const float A    = h * coef;                      // p_hit = A * exp(-lam*v)
    const float c1   = 1.0f - h;

    const size_t base_obs = (size_t)e * (size_t)n_per + (size_t)start;

    float acc_log = 0.0f;
    float acc_hit = 0.0f;

    const int tid = threadIdx.x;

    // Fast path: 4 observations per iteration via 3x float4 per array.
    int scalar_begin = 0;
    if ((base_obs & 3u) == 0u) {
        const int n_groups = count >> 2;           // groups of 4 obs
        scalar_begin = n_groups << 2;
        const float4* __restrict__ p4 = (const float4*)(u_pred + base_obs * 3);
        const float4* __restrict__ o4 = (const float4*)(u_obs  + base_obs * 3);

        #pragma unroll 2
        for (int g = tid; g < n_groups; g += THREADS) {
            const size_t fb = (size_t)g * 3;
            float4 a0 = __ldg(&p4[fb + 0]);
            float4 a1 = __ldg(&p4[fb + 1]);
            float4 a2 = __ldg(&p4[fb + 2]);
            float4 b0 = __ldg(&o4[fb + 0]);
            float4 b1 = __ldg(&o4[fb + 1]);
            float4 b2 = __ldg(&o4[fb + 2]);

            float dx[4], dy[4], dz[4];
            dx[0] = a0.x - b0.x; dy[0] = a0.y - b0.y; dz[0] = a0.z - b0.z;
            dx[1] = a0.w - b0.w; dy[1] = a1.x - b1.x; dz[1] = a1.y - b1.y;
            dx[2] = a1.z - b1.z; dy[2] = a1.w - b1.w; dz[2] = a2.x - b2.x;
            dx[3] = a2.y - b2.y; dy[3] = a2.z - b2.z; dz[3] = a2.w - b2.w;

            #pragma unroll
            for (int j = 0; j < 4; ++j) {
                float s2 = dx[j]*dx[j];
                s2 = fmaf(dy[j], dy[j], s2);
                s2 = fmaf(dz[j], dz[j], s2);
                const bool close = s2 < th;
                const float v   = s2 * inv_th;
                const float em  = __expf(-lam * v);
                const float ph  = A * em;
                const float p   = ph + c1;
                const float lp  = __logf(p);
                const float post = __fdividef(ph, p);
                acc_log += close ? lp : 0.0f;
                acc_hit += (close && post > 0.95f) ? post : 0.0f;
            }
        }
    }

    // Scalar tail (covers misaligned bases and count % 4)
    for (int i = scalar_begin + tid; i < count; i += THREADS) {
        const size_t o = (base_obs + (size_t)i) * 3;
        const float dx = __ldg(&u_pred[o + 0]) - __ldg(&u_obs[o + 0]);
        const float dy = __ldg(&u_pred[o + 1]) - __ldg(&u_obs[o + 1]);
        const float dz = __ldg(&u_pred[o + 2]) - __ldg(&u_obs[o + 2]);
        float s2 = dx*dx; s2 = fmaf(dy, dy, s2); s2 = fmaf(dz, dz, s2);
        const bool close = s2 < th;
        const float v   = s2 * inv_th;
        const float em  = __expf(-lam * v);
        const float ph  = A * em;
        const float p   = ph + c1;
        const float lp  = __logf(p);
        const float post = __fdividef(ph, p);
        acc_log += close ? lp : 0.0f;
        acc_hit += (close && post > 0.95f) ? post : 0.0f;
    }

    // Deterministic block reduction (fixed shuffle tree)
    __shared__ float s_log[THREADS / 32];
    __shared__ float s_hit[THREADS / 32];
    __shared__ int   s_last;
    const int lane = tid & 31;
    const int wid  = tid >> 5;
    #pragma unroll
    for (int off = 16; off > 0; off >>= 1) {
        acc_log += __shfl_down_sync(0xFFFFFFFFu, acc_log, off);
        acc_hit += __shfl_down_sync(0xFFFFFFFFu, acc_hit, off);
    }
    if (lane == 0) { s_log[wid] = acc_log; s_hit[wid] = acc_hit; }
    __syncthreads();
    if (wid == 0) {
        float vlog = (lane < THREADS / 32) ? s_log[lane] : 0.0f;
        float vhit = (lane < THREADS / 32) ? s_hit[lane] : 0.0f;
        #pragma unroll
        for (int off = 2; off > 0; off >>= 1) {
            vlog += __shfl_down_sync(0xFFFFFFFFu, vlog, off);
            vhit += __shfl_down_sync(0xFFFFFFFFu, vhit, off);
        }
        if (lane == 0) {
            g_partial_log[e * MAX_CHUNKS + c] = vlog;
            g_partial_hit[e * MAX_CHUNKS + c] = vhit;
            __threadfence();
            // last-block-done: old == n_chunks-1 means all partials visible
            int old = atomicAdd(&g_count[e], 1);
            s_last = (old == n_chunks - 1) ? 1 : 0;
        }
    }
    __syncthreads();

    if (s_last) {
        // Finisher block: deterministic fixed-tree sum over chunk partials.
        if (wid == 0) {
            __threadfence();  // acquire partials
            float vlog = (lane < n_chunks) ? g_partial_log[e * MAX_CHUNKS + lane] : 0.0f;
            float vhit = (lane < n_chunks) ? g_partial_hit[e * MAX_CHUNKS + lane] : 0.0f;
            #pragma unroll
            for (int off = 16; off > 0; off >>= 1) {
                vlog += __shfl_down_sync(0xFFFFFFFFu, vlog, off);
                vhit += __shfl_down_sync(0xFFFFFFFFu, vhit, off);
            }
            if (lane == 0) {
                out[e]         = vlog;   // log_like
                out[B + e]     = vhit;   // hits
                out[2 * B + e] = vhit;   // hits_raw
                g_count[e] = 0;          // reset for next graph replay
            }
        }
    }
}

extern "C" void kernel_launch(void* const* d_in, const int* in_sizes, int n_in,
                              void* d_out, int out_size)
{
    const float* u_pred = (const float*)d_in[0];
    const float* u_obs  = (const float*)d_in[1];
    const float* h      = (const float*)d_in[2];
    const float* lam    = (const float*)d_in[3];
    const float* th     = (const float*)d_in[4];

    const int N = in_sizes[0] / 3;          // observations
    const int B = in_sizes[2];              // elements (64)
    const int n_per = N / B;                // 100000

    // 1920 blocks of 128 threads ~= one full reg-limited wave (13 blocks/SM x 148 SMs)
    int n_chunks = 30;                      // must be <= 32 (warp-tree finisher)
    if (n_chunks > MAX_CHUNKS) n_chunks = MAX_CHUNKS;
    int chunk = (n_per + n_chunks - 1) / n_chunks;
    chunk = (chunk + 3) & ~3;               // multiple of 4 keeps float4 alignment
    n_chunks = (n_per + chunk - 1) / chunk;

    dim3 grid(B, n_chunks);
    traj_score_fused<<<grid, THREADS>>>(u_pred, u_obs, h, lam, th,
                                        (float*)d_out, n_per, chunk, n_chunks, B);
}

// round 4
// speedup vs baseline: 1.0812x; 1.0812x over previous
#include <cuda_runtime.h>
#include <cstdint>

// Deterministic cross-chunk reduction scratch (no alloc, no float atomics).
#define MAX_B      64
#define MAX_CHUNKS 32
#define N_CHUNKS   9
__device__ float g_partial_log[MAX_B * MAX_CHUNKS];
__device__ float g_partial_hit[MAX_B * MAX_CHUNKS];
__device__ int   g_count[MAX_B];          // zero-init; self-resetting per replay

#define THREADS 256

__global__ __launch_bounds__(THREADS)
void traj_score_fused(const float* __restrict__ u_pred,
                      const float* __restrict__ u_obs,
                      const float* __restrict__ h_arr,
                      const float* __restrict__ lam_arr,
                      const float* __restrict__ th_arr,
                      float* __restrict__ out,
                      int n_per, int chunk, int n_chunks, int B)
{
    const int e = blockIdx.x;           // element / segment id
    const int c = blockIdx.y;           // chunk id within segment
    const int start = c * chunk;
    int end = start + chunk;
    if (end > n_per) end = n_per;
    const int count = end - start;

    // Per-element constants
    const float h    = __ldg(&h_arr[e]);
    const float lam  = __ldg(&lam_arr[e]);
    const float th   = __ldg(&th_arr[e]);
    const float inv_th = 1.0f / th;
    const float karg = -lam * inv_th;                 // exp arg = s2 * karg
    const float coef = lam / (1.0f - __expf(-lam));   // lam / (1 - e^-lam)
    const float A    = h * coef;                      // p_hit = A * exp(-lam*v)
    const float c1   = 1.0f - h;

    const size_t base_obs = (size_t)e * (size_t)n_per + (size_t)start;

    float acc_log = 0.0f;
    float acc_hit = 0.0f;

    const int tid = threadIdx.x;

    // Fast path: software-pipelined, 4 obs per iteration via 3x float4 per array.
    // While computing group g, the 6 loads for g+THREADS are in flight.
    int scalar_begin = 0;
    if ((base_obs & 3u) == 0u) {
        const int n_groups = count >> 2;           // groups of 4 obs
        scalar_begin = n_groups << 2;
        const float4* __restrict__ p4 = (const float4*)(u_pred + base_obs * 3);
        const float4* __restrict__ o4 = (const float4*)(u_obs  + base_obs * 3);

        int g = tid;
        float4 a0, a1, a2, b0, b1, b2;
        bool have = g < n_groups;
        if (have) {
            const size_t fb = (size_t)g * 3;
            a0 = __ldg(&p4[fb + 0]); a1 = __ldg(&p4[fb + 1]); a2 = __ldg(&p4[fb + 2]);
            b0 = __ldg(&o4[fb + 0]); b1 = __ldg(&o4[fb + 1]); b2 = __ldg(&o4[fb + 2]);
        }
        while (have) {
            const int gn = g + THREADS;
            const bool haven = gn < n_groups;
            float4 na0, na1, na2, nb0, nb1, nb2;
            if (haven) {
                const size_t fb = (size_t)gn * 3;
                na0 = __ldg(&p4[fb + 0]); na1 = __ldg(&p4[fb + 1]); na2 = __ldg(&p4[fb + 2]);
                nb0 = __ldg(&o4[fb + 0]); nb1 = __ldg(&o4[fb + 1]); nb2 = __ldg(&o4[fb + 2]);
            }

            // Compute on current registers (4 observations)
            float s2q[4];
            {
                float dx, dy, dz;
                dx = a0.x - b0.x; dy = a0.y - b0.y; dz = a0.z - b0.z;
                s2q[0] = fmaf(dz, dz, fmaf(dy, dy, dx * dx));
                dx = a0.w - b0.w; dy = a1.x - b1.x; dz = a1.y - b1.y;
                s2q[1] = fmaf(dz, dz, fmaf(dy, dy, dx * dx));
                dx = a1.z - b1.z; dy = a1.w - b1.w; dz = a2.x - b2.x;
                s2q[2] = fmaf(dz, dz, fmaf(dy, dy, dx * dx));
                dx = a2.y - b2.y; dy = a2.z - b2.z; dz = a2.w - b2.w;
                s2q[3] = fmaf(dz, dz, fmaf(dy, dy, dx * dx));
            }
            #pragma unroll
            for (int j = 0; j < 4; ++j) {
                const float s2  = s2q[j];
                const bool close = s2 < th;
                const float em  = __expf(s2 * karg);      // exp(-lam * s2/th)
                const float ph  = A * em;
                const float p   = ph + c1;
                const float lp  = __logf(p);
                const float post = __fdividef(ph, p);
                acc_log += close ? lp : 0.0f;
                acc_hit += (close && post > 0.95f) ? post : 0.0f;
            }

            a0 = na0; a1 = na1; a2 = na2;
            b0 = nb0; b1 = nb1; b2 = nb2;
            g = gn; have = haven;
        }
    }

    // Scalar tail (covers misaligned bases and count % 4; normally empty)
    for (int i = scalar_begin + tid; i < count; i += THREADS) {
        const size_t o = (base_obs + (size_t)i) * 3;
        const float dx = __ldg(&u_pred[o + 0]) - __ldg(&u_obs[o + 0]);
        const float dy = __ldg(&u_pred[o + 1]) - __ldg(&u_obs[o + 1]);
        const float dz = __ldg(&u_pred[o + 2]) - __ldg(&u_obs[o + 2]);
        float s2 = dx*dx; s2 = fmaf(dy, dy, s2); s2 = fmaf(dz, dz, s2);
        const bool close = s2 < th;
        const float em  = __expf(s2 * karg);
        const float ph  = A * em;
        const float p   = ph + c1;
        const float lp  = __logf(p);
        const float post = __fdividef(ph, p);
        acc_log += close ? lp : 0.0f;
        acc_hit += (close && post > 0.95f) ? post : 0.0f;
    }

    // Deterministic block reduction (fixed shuffle tree)
    __shared__ float s_log[THREADS / 32];
    __shared__ float s_hit[THREADS / 32];
    __shared__ int   s_last;
    const int lane = tid & 31;
    const int wid  = tid >> 5;
    #pragma unroll
    for (int off = 16; off > 0; off >>= 1) {
        acc_log += __shfl_down_sync(0xFFFFFFFFu, acc_log, off);
        acc_hit += __shfl_down_sync(0xFFFFFFFFu, acc_hit, off);
    }
    if (lane == 0) { s_log[wid] = acc_log; s_hit[wid] = acc_hit; }
    __syncthreads();
    if (wid == 0) {
        float vlog = (lane < THREADS / 32) ? s_log[lane] : 0.0f;
        float vhit = (lane < THREADS / 32) ? s_hit[lane] : 0.0f;
        #pragma unroll
        for (int off = 4; off > 0; off >>= 1) {
            vlog += __shfl_down_sync(0xFFFFFFFFu, vlog, off);
            vhit += __shfl_down_sync(0xFFFFFFFFu, vhit, off);
        }
        if (lane == 0) {
            g_partial_log[e * MAX_CHUNKS + c] = vlog;
            g_partial_hit[e * MAX_CHUNKS + c] = vhit;
            __threadfence();
            // last-block-done: old == n_chunks-1 means all partials visible
            int old = atomicAdd(&g_count[e], 1);
            s_last = (old == n_chunks - 1) ? 1 : 0;
        }
    }
    __syncthreads();

    if (s_last) {
        // Finisher block: deterministic fixed-tree sum over chunk partials.
        if (wid == 0) {
            __threadfence();  // acquire partials
            float vlog = (lane < n_chunks) ? g_partial_log[e * MAX_CHUNKS + lane] : 0.0f;
            float vhit = (lane < n_chunks) ? g_partial_hit[e * MAX_CHUNKS + lane] : 0.0f;
            #pragma unroll
            for (int off = 16; off > 0; off >>= 1) {
                vlog += __shfl_down_sync(0xFFFFFFFFu, vlog, off);
                vhit += __shfl_down_sync(0xFFFFFFFFu, vhit, off);
            }
            if (lane == 0) {
                out[e]         = vlog;   // log_like
                out[B + e]     = vhit;   // hits
                out[2 * B + e] = vhit;   // hits_raw
                g_count[e] = 0;          // reset for next graph replay
            }
        }
    }
}

extern "C" void kernel_launch(void* const* d_in, const int* in_sizes, int n_in,
                              void* d_out, int out_size)
{
    const float* u_pred = (const float*)d_in[0];
    const float* u_obs  = (const float*)d_in[1];
    const float* h      = (const float*)d_in[2];
    const float* lam    = (const float*)d_in[3];
    const float* th     = (const float*)d_in[4];

    const int N = in_sizes[0] / 3;          // observations
    const int B = in_sizes[2];              // elements (64)
    const int n_per = N / B;                // 100000

    // ~576 blocks of 256 threads ~= one full wave at ~4 blocks/SM (regs ~64)
    int n_chunks = N_CHUNKS;                // must be <= 32 (warp-tree finisher)
    if (n_chunks > MAX_CHUNKS) n_chunks = MAX_CHUNKS;
    int chunk = (n_per + n_chunks - 1) / n_chunks;
    chunk = (chunk + 3) & ~3;               // multiple of 4 keeps float4 alignment
    n_chunks = (n_per + chunk - 1) / chunk;

    dim3 grid(B, n_chunks);
    traj_score_fused<<<grid, THREADS>>>(u_pred, u_obs, h, lam, th,
                                        (float*)d_out, n_per, chunk, n_chunks, B);
}

// round 5
// speedup vs baseline: 1.1241x; 1.0397x over previous
#include <cuda_runtime.h>
#include <cstdint>

// Deterministic cross-chunk reduction scratch (no alloc, no float atomics).
#define MAX_B      64
#define MAX_CHUNKS 32
__device__ float g_partial_log[MAX_B * MAX_CHUNKS];
__device__ float g_partial_hit[MAX_B * MAX_CHUNKS];
__device__ int   g_count[MAX_B];          // zero-init; self-resetting per replay

#define THREADS   128
#define OBS_PER_T 4
#define TILE_OBS  (THREADS * OBS_PER_T)     // 512 obs per stage
#define TILE_F4   (TILE_OBS * 3 / 4)        // 384 float4 per array per stage
#define STAGES    3

__device__ __forceinline__ void cp_async16(void* smem_dst, const void* gsrc) {
    uint32_t s = (uint32_t)__cvta_generic_to_shared(smem_dst);
    asm volatile("cp.async.cg.shared.global [%0], [%1], 16;\n" :: "r"(s), "l"(gsrc));
}
__device__ __forceinline__ void cp_commit() {
    asm volatile("cp.async.commit_group;\n" ::: "memory");
}
__device__ __forceinline__ void cp_wait1() {
    asm volatile("cp.async.wait_group 1;\n" ::: "memory");
}

__global__ __launch_bounds__(THREADS)
void traj_score_fused(const float* __restrict__ u_pred,
                      const float* __restrict__ u_obs,
                      const float* __restrict__ h_arr,
                      const float* __restrict__ lam_arr,
                      const float* __restrict__ th_arr,
                      float* __restrict__ out,
                      int n_per, int chunk, int n_chunks, int B)
{
    __shared__ float4 s_p[STAGES][TILE_F4];
    __shared__ float4 s_o[STAGES][TILE_F4];

    const int e = blockIdx.x;           // element / segment id
    const int c = blockIdx.y;           // chunk id within segment
    const int start = c * chunk;
    int end = start + chunk;
    if (end > n_per) end = n_per;
    const int count = end - start;

    // Per-element constants
    const float h    = __ldg(&h_arr[e]);
    const float lam  = __ldg(&lam_arr[e]);
    const float th   = __ldg(&th_arr[e]);
    const float inv_th = 1.0f / th;
    const float karg = -lam * inv_th;                 // exp arg = s2 * karg
    const float coef = lam / (1.0f - __expf(-lam));   // lam / (1 - e^-lam)
    const float A    = h * coef;                      // p_hit = A * exp(-lam*v)
    const float c1   = 1.0f - h;

    const size_t base_obs = (size_t)e * (size_t)n_per + (size_t)start;
    const int tid = threadIdx.x;

    float acc_log = 0.0f;
    float acc_hit = 0.0f;

    if (((base_obs * 3) & 3u) == 0u) {
        // ---- staged cp.async path (always taken for this problem's shapes) ----
        const float4* __restrict__ gp4 = (const float4*)u_pred;
        const float4* __restrict__ go4 = (const float4*)u_obs;
        const long f4_base = (long)(base_obs * 3 / 4);
        const long f4_max  = f4_base + (long)count * 3 / 4;   // exclusive
        const int n_it = (count + TILE_OBS - 1) / TILE_OBS;

        // stage issue: contiguous, clamped to segment
        auto issue = [&](int slot, int it) {
            const long fb = f4_base + (long)it * TILE_F4;
            #pragma unroll
            for (int k = 0; k < 3; ++k) {
                long idx = fb + k * THREADS + tid;
                if (idx >= f4_max) idx = f4_max - 1;    // clamp (dup load, in-bounds)
                cp_async16(&s_p[slot][k * THREADS + tid], &gp4[idx]);
                cp_async16(&s_o[slot][k * THREADS + tid], &go4[idx]);
            }
        };

        // prologue: fill STAGES-1 stages
        #pragma unroll
        for (int s = 0; s < STAGES - 1; ++s) {
            if (s < n_it) issue(s, s);
            cp_commit();
        }

        for (int it = 0; it < n_it; ++it) {
            const int slot = it % STAGES;
            cp_wait1();            // stage `it` complete (≤1 group outstanding)
            __syncthreads();       // visible to all; also frees slot (it+2)%STAGES

            // issue next stage early to overlap with compute
            const int nxt = it + (STAGES - 1);
            if (nxt < n_it) issue(nxt % STAGES, nxt);
            cp_commit();

            // compute 4 obs from this thread's 3 float4s (conflict-free LDS.128)
            const float4 a0 = s_p[slot][3 * tid + 0];
            const float4 a1 = s_p[slot][3 * tid + 1];
            const float4 a2 = s_p[slot][3 * tid + 2];
            const float4 b0 = s_o[slot][3 * tid + 0];
            const float4 b1 = s_o[slot][3 * tid + 1];
            const float4 b2 = s_o[slot][3 * tid + 2];

            float s2q[4];
            {
                float dx, dy, dz;
                dx = a0.x - b0.x; dy = a0.y - b0.y; dz = a0.z - b0.z;
                s2q[0] = fmaf(dz, dz, fmaf(dy, dy, dx * dx));
                dx = a0.w - b0.w; dy = a1.x - b1.x; dz = a1.y - b1.y;
                s2q[1] = fmaf(dz, dz, fmaf(dy, dy, dx * dx));
                dx = a1.z - b1.z; dy = a1.w - b1.w; dz = a2.x - b2.x;
                s2q[2] = fmaf(dz, dz, fmaf(dy, dy, dx * dx));
                dx = a2.y - b2.y; dy = a2.z - b2.z; dz = a2.w - b2.w;
                s2q[3] = fmaf(dz, dz, fmaf(dy, dy, dx * dx));
            }

            const int ob = it * TILE_OBS + OBS_PER_T * tid;
            #pragma unroll
            for (int j = 0; j < 4; ++j) {
                const float s2   = s2q[j];
                const bool valid = (ob + j) < count;
                const bool close = valid && (s2 < th);
                const float em   = __expf(s2 * karg);   // exp(-lam * s2/th)
                const float ph   = A * em;
                const float p    = ph + c1;
                const float lp   = __logf(p);
                const float post = __fdividef(ph, p);
                acc_log += close ? lp : 0.0f;
                acc_hit += (close && post > 0.95f) ? post : 0.0f;
            }
        }
    } else {
        // ---- defensive scalar fallback (not expected to run) ----
        for (int i = tid; i < count; i += THREADS) {
            const size_t o = (base_obs + (size_t)i) * 3;
            const float dx = __ldg(&u_pred[o + 0]) - __ldg(&u_obs[o + 0]);
            const float dy = __ldg(&u_pred[o + 1]) - __ldg(&u_obs[o + 1]);
            const float dz = __ldg(&u_pred[o + 2]) - __ldg(&u_obs[o + 2]);
            float s2 = dx*dx; s2 = fmaf(dy, dy, s2); s2 = fmaf(dz, dz, s2);
            const bool close = s2 < th;
            const float em  = __expf(s2 * karg);
            const float ph  = A * em;
            const float p   = ph + c1;
            const float lp  = __logf(p);
            const float post = __fdividef(ph, p);
            acc_log += close ? lp : 0.0f;
            acc_hit += (close && post > 0.95f) ? post : 0.0f;
        }
    }

    // Deterministic block reduction (fixed shuffle tree)
    __shared__ float s_log[THREADS / 32];
    __shared__ float s_hit[THREADS / 32];
    __shared__ int   s_last;
    const int lane = tid & 31;
    const int wid  = tid >> 5;
    #pragma unroll
    for (int off = 16; off > 0; off >>= 1) {
        acc_log += __shfl_down_sync(0xFFFFFFFFu, acc_log, off);
        acc_hit += __shfl_down_sync(0xFFFFFFFFu, acc_hit, off);
    }
    if (lane == 0) { s_log[wid] = acc_log; s_hit[wid] = acc_hit; }
    __syncthreads();
    if (wid == 0) {
        float vlog = (lane < THREADS / 32) ? s_log[lane] : 0.0f;
        float vhit = (lane < THREADS / 32) ? s_hit[lane] : 0.0f;
        #pragma unroll
        for (int off = 2; off > 0; off >>= 1) {
            vlog += __shfl_down_sync(0xFFFFFFFFu, vlog, off);
            vhit += __shfl_down_sync(0xFFFFFFFFu, vhit, off);
        }
        if (lane == 0) {
            g_partial_log[e * MAX_CHUNKS + c] = vlog;
            g_partial_hit[e * MAX_CHUNKS + c] = vhit;
            __threadfence();
            int old = atomicAdd(&g_count[e], 1);
            s_last = (old == n_chunks - 1) ? 1 : 0;
        }
    }
    __syncthreads();

    if (s_last) {
        // Finisher block: deterministic fixed-tree sum over chunk partials.
        if (wid == 0) {
            __threadfence();  // acquire partials
            float vlog = (lane < n_chunks) ? g_partial_log[e * MAX_CHUNKS + lane] : 0.0f;
            float vhit = (lane < n_chunks) ? g_partial_hit[e * MAX_CHUNKS + lane] : 0.0f;
            #pragma unroll
            for (int off = 16; off > 0; off >>= 1) {
                vlog += __shfl_down_sync(0xFFFFFFFFu, vlog, off);
                vhit += __shfl_down_sync(0xFFFFFFFFu, vhit, off);
            }
            if (lane == 0) {
                out[e]         = vlog;   // log_like
                out[B + e]     = vhit;   // hits
                out[2 * B + e] = vhit;   // hits_raw
                g_count[e] = 0;          // reset for next graph replay
            }
        }
    }
}

extern "C" void kernel_launch(void* const* d_in, const int* in_sizes, int n_in,
                              void* d_out, int out_size)
{
    const float* u_pred = (const float*)d_in[0];
    const float* u_obs  = (const float*)d_in[1];
    const float* h      = (const float*)d_in[2];
    const float* lam    = (const float*)d_in[3];
    const float* th     = (const float*)d_in[4];

    const int N = in_sizes[0] / 3;          // observations
    const int B = in_sizes[2];              // elements (64)
    const int n_per = N / B;                // 100000

    // chunk multiple of TILE_OBS(512); ~28 chunks -> fine-grained self-balancing grid
    int n_chunks = 28;
    if (n_chunks > MAX_CHUNKS) n_chunks = MAX_CHUNKS;
    int chunk = (n_per + n_chunks - 1) / n_chunks;
    chunk = (chunk + TILE_OBS - 1) & ~(TILE_OBS - 1);
    n_chunks = (n_per + chunk - 1) / chunk;

    dim3 grid(B, n_chunks);
    traj_score_fused<<<grid, THREADS>>>(u_pred, u_obs, h, lam, th,
                                        (float*)d_out, n_per, chunk, n_chunks, B);
}